// round 6
// baseline (speedup 1.0000x reference)
#include <cuda_runtime.h>
#include <cuda_bf16.h>
#include <cstdint>

// Problem constants (fixed by the dataset)
#define B 64
#define S 8192
#define C 48
#define L 42
#define LP1 (L + 1)          // 43
#define IGNORE_LBL (-100)

#define THREADS 256
#define WARPS   (THREADS / 32)       // 8
#define NCH     16                   // chunks per row
#define CHUNK   (S / NCH)            // 512
#define SUBS    (CHUNK / THREADS)    // 2 positions per thread
#define NSEG    (SUBS * WARPS)       // 16 warp-segments per chunk
#define NCHT    (B * NCH)            // 1024 blocks

// ---------------------------------------------------------------------------
// Device-global scratch
// ---------------------------------------------------------------------------
__device__ double   g_partial[NCHT];   // per-chunk raw score partial (emis + raw trans)
__device__ int      g_pcount[NCHT];    // per-chunk valid-token count
__device__ int      g_first[NCHT];     // per-chunk first valid label (-1 if none)
__device__ int      g_last[NCHT];      // per-chunk last valid label
__device__ int      g_hist[L];         // global transition-source histogram (zero-init)
__device__ unsigned g_ticket;          // finish counter (reset by last block)

// ---------------------------------------------------------------------------
// One block per (row, chunk). 1024 blocks x 256 threads = single balanced wave.
// Blocks accumulate RAW arc scores + a source-row histogram; the final block
// computes the 43 log-sum-exps once and applies the normalization:
//   normalized_sum = raw_sum - sum_r hist[r] * lse[r]  (+ start/final terms)
// ---------------------------------------------------------------------------
__global__ __launch_bounds__(THREADS, 8)
void crf_fused_kernel(const float* log_probs,
                      const float* __restrict__ A_scores,
                      const int*   __restrict__ labels,
                      float*       __restrict__ out) {
    const int cid  = blockIdx.x;
    const int b    = cid / NCH;
    const int ch   = cid % NCH;
    const int tid  = threadIdx.x;
    const int lane = tid & 31;
    const int wid  = tid >> 5;

    __shared__ float  A_sh[L + L * LP1];   // 1848 raw scores
    __shared__ int    hist_sh[L];
    __shared__ int    seg_first[NSEG];
    __shared__ int    seg_last[NSEG];
    __shared__ double red[WARPS];
    __shared__ int    redc[WARPS];
    __shared__ int    is_last;
    __shared__ float  lse_sh[LP1];         // last block only
    __shared__ double row_sum[B];          // last block only
    __shared__ int    row_cnt[B];          // last block only

    // ---- 1. zero hist, stage A_scores, issue label loads ----
    if (tid < L) hist_sh[tid] = 0;
    #pragma unroll
    for (int i = tid; i < L + L * LP1; i += THREADS) A_sh[i] = A_scores[i];

    const int* lab = labels + (size_t)b * S + (size_t)ch * CHUNK;
    int ys[SUBS];
    #pragma unroll
    for (int i = 0; i < SUBS; i++) ys[i] = __ldg(lab + i * THREADS + tid);

    __syncthreads();   // A_sh + hist ready (label LDGs in flight)

    // ---- 2. issue emission gathers as soon as labels land ----
    const float* lpb = log_probs + (size_t)b * S * C + (size_t)ch * CHUNK * C;
    float emis[SUBS];
    #pragma unroll
    for (int i = 0; i < SUBS; i++) {
        int p = i * THREADS + tid;
        emis[i] = (ys[i] != IGNORE_LBL) ? lpb[(size_t)p * C + ys[i]] : 0.0f;
    }

    // ---- 3. intra-warp transitions (raw) + histogram + segment endpoints ----
    double local = 0.0;
    int    cnt   = 0;
    #pragma unroll
    for (int i = 0; i < SUBS; i++) {
        int y = ys[i];
        bool valid = (y != IGNORE_LBL);
        cnt += valid ? 1 : 0;

        unsigned m = __ballot_sync(0xffffffffu, valid);
        unsigned rest = m & (0xFFFFFFFEu << lane);   // valid lanes strictly after me
        int partner = rest ? (__ffs(rest) - 1) : -1;
        int ynext = __shfl_sync(0xffffffffu, y, partner & 31);
        if (valid && partner >= 0) {
            local += (double)A_sh[L + (y - 1) * LP1 + (ynext - 1)];
            atomicAdd(&hist_sh[y - 1], 1);
        }

        int firstlane = __ffs(m) - 1;
        int lastlane  = 31 - __clz(m | 1u);
        int yf = __shfl_sync(0xffffffffu, y, firstlane & 31);
        int yl = __shfl_sync(0xffffffffu, y, lastlane & 31);
        if (lane == 0) {
            int seg = i * WARPS + wid;     // position order
            seg_first[seg] = m ? yf : -1;
            seg_last[seg]  = m ? yl : -1;
        }
    }
    __syncthreads();

    // ---- 4. warp-boundary stitching (warp 0, all 16 segments in parallel) ----
    if (wid == 0) {
        bool ne = (lane < NSEG) && (seg_first[lane] >= 0);
        unsigned m = __ballot_sync(0xffffffffu, ne);
        if (ne) {
            unsigned low = m & ((1u << lane) - 1u);
            if (low) {
                int pred = 31 - __clz(low);
                int y1 = seg_last[pred], y2 = seg_first[lane];
                local += (double)A_sh[L + (y1 - 1) * LP1 + (y2 - 1)];
                atomicAdd(&hist_sh[y1 - 1], 1);
            }
        }
        if (lane == 0) {
            g_first[cid] = m ? seg_first[__ffs(m) - 1] : -1;
            g_last[cid]  = m ? seg_last[31 - __clz(m)] : -1;
        }
    }

    // ---- 5. fold emissions, block reduce ----
    #pragma unroll
    for (int i = 0; i < SUBS; i++) local += (double)emis[i];
    #pragma unroll
    for (int o = 16; o > 0; o >>= 1) {
        local += __shfl_down_sync(0xffffffffu, local, o);
        cnt   += __shfl_down_sync(0xffffffffu, cnt, o);
    }
    if (lane == 0) { red[wid] = local; redc[wid] = cnt; }
    __syncthreads();

    if (wid == 0) {
        double v = (lane < WARPS) ? red[lane] : 0.0;
        int    c = (lane < WARPS) ? redc[lane] : 0;
        #pragma unroll
        for (int o = 4; o > 0; o >>= 1) {
            v += __shfl_down_sync(0xffffffffu, v, o);
            c += __shfl_down_sync(0xffffffffu, c, o);
        }
        if (lane == 0) { g_partial[cid] = v; g_pcount[cid] = c; }
    }
    // flush histogram (hist_sh complete: step-3 atomics before the barrier
    // above; step-4 atomics by warp 0, which also executes this after them)
    if (tid < L) {
        int h = hist_sh[tid];
        if (h) atomicAdd(&g_hist[tid], h);
    }
    __threadfence();   // every writer orders its own globals before the ticket
    __syncthreads();
    if (tid == 0) {
        unsigned t = atomicAdd(&g_ticket, 1u);
        is_last = (t == NCHT - 1) ? 1 : 0;
    }
    __syncthreads();

    // ---- 6. last block: LSEs once, stitch chunks, normalize, finalize ----
    if (is_last) {
        __threadfence();
        // 43 LSEs: thread r < 42 -> transition row r; r == 42 -> start row.
        // (A_scores are 0.1*normal; no max-subtraction needed.)
        if (tid < LP1) {
            float s = 0.0f;
            if (tid < L) {
                const float* row = A_sh + L + tid * LP1;
                #pragma unroll
                for (int j = 0; j < LP1; j++) s += __expf(row[j]);
            } else {
                #pragma unroll
                for (int j = 0; j < L; j++) s += __expf(A_sh[j]);
            }
            lse_sh[tid] = __logf(s);
        }
        __syncthreads();

        if (tid < B) {
            double s = 0.0; int c = 0, prev = -1, f0 = -1;
            #pragma unroll 4
            for (int k = 0; k < NCH; k++) {
                int idx = tid * NCH + k;
                s += g_partial[idx];
                c += g_pcount[idx];
                int f = g_first[idx];
                if (f >= 0) {
                    if (prev >= 0)
                        s += (double)(A_sh[L + (prev - 1) * LP1 + (f - 1)] - lse_sh[prev - 1]);
                    else f0 = f;
                    prev = g_last[idx];
                }
            }
            if (f0 >= 0) {
                s += (double)(A_sh[f0 - 1] - lse_sh[L]);                          // start
                s += (double)(A_sh[L + (prev - 1) * LP1 + L] - lse_sh[prev - 1]); // final
            }
            row_sum[tid] = s;
            row_cnt[tid] = c;
        }
        __syncthreads();

        if (wid == 0) {
            double s = row_sum[lane] + row_sum[lane + 32];
            int    c = row_cnt[lane] + row_cnt[lane + 32];
            // histogram correction: - sum_r hist[r] * lse[r]
            double corr = (lane < L) ? (double)g_hist[lane] * (double)lse_sh[lane] : 0.0;
            if (lane + 32 < L) corr += (double)g_hist[lane + 32] * (double)lse_sh[lane + 32];
            #pragma unroll
            for (int o = 16; o > 0; o >>= 1) {
                s    += __shfl_down_sync(0xffffffffu, s, o);
                c    += __shfl_down_sync(0xffffffffu, c, o);
                corr += __shfl_down_sync(0xffffffffu, corr, o);
            }
            if (lane == 0) {
                out[0] = (float)((s - corr) / (double)c);
                g_ticket = 0;   // reset for graph replay
            }
        }
        __syncthreads();
        if (tid < L) g_hist[tid] = 0;   // reset for graph replay
    }
}

// ---------------------------------------------------------------------------
// Launch
// ---------------------------------------------------------------------------
extern "C" void kernel_launch(void* const* d_in, const int* in_sizes, int n_in,
                              void* d_out, int out_size) {
    const float* log_probs = (const float*)d_in[0];   // (B, S, C) f32
    const float* A_scores  = (const float*)d_in[1];   // (N_ARCS,) f32
    const int*   labels    = (const int*)d_in[2];     // (B, S) i32
    float* out = (float*)d_out;

    crf_fused_kernel<<<NCHT, THREADS>>>(log_probs, A_scores, labels, out);
}

// round 7
// speedup vs baseline: 1.0097x; 1.0097x over previous
#include <cuda_runtime.h>
#include <cuda_bf16.h>
#include <cstdint>

// Problem constants (fixed by the dataset)
#define B 64
#define S 8192
#define C 48
#define L 42
#define LP1 (L + 1)          // 43
#define IGNORE_LBL (-100)

#define THREADS 512
#define WARPS   (THREADS / 32)        // 16
#define NBLK    592                   // 4 blocks on each of 148 SMs
#define CHUNK   512                   // positions per work item (1 per thread)
#define NCHUNK  (B * S / CHUNK)       // 1024 work items; 16 per row

// ---------------------------------------------------------------------------
// Device-global scratch
// ---------------------------------------------------------------------------
__device__ double   g_partial[NBLK];   // per-block normalized partial
__device__ int      g_pcount[NBLK];    // per-block valid-token count
__device__ int      g_first[NCHUNK];   // per-chunk first valid label (-1 if none)
__device__ int      g_last[NCHUNK];    // per-chunk last valid label
__device__ unsigned g_work;            // work-stealing ticket (reset by last block)
__device__ unsigned g_ticket;          // finish counter (reset by last block)

// ---------------------------------------------------------------------------
// Persistent kernel: 592 blocks x 512 threads, dynamic over 1024 chunks.
// Chunks are contiguous in the flat [B*S] position space, so chunk t covers
// global positions [t*512, (t+1)*512) and row b = t/16 (16 chunks per row).
// ---------------------------------------------------------------------------
__global__ __launch_bounds__(THREADS, 4)
void crf_fused_kernel(const float* log_probs,
                      const float* __restrict__ A_scores,
                      const int*   __restrict__ labels,
                      float*       __restrict__ out) {
    const int tid  = threadIdx.x;
    const int lane = tid & 31;
    const int wid  = tid >> 5;

    __shared__ float  A_sh[L + L * LP1];   // 1848 raw scores
    __shared__ float  lse_sh[LP1];
    __shared__ int    hist_sh[L];          // transition-source histogram (block-local)
    __shared__ int    seg_f[WARPS];
    __shared__ int    seg_l[WARPS];
    __shared__ double red[WARPS];
    __shared__ int    redc[WARPS];
    __shared__ int    tick_sh;
    __shared__ int    is_last;
    __shared__ double row_sum[B];          // last block only
    __shared__ int    row_cnt[B];          // last block only

    // ---- 1. steal first chunk, zero hist, stage A_scores ----
    if (tid == 0) tick_sh = (int)atomicAdd(&g_work, 1u);
    if (tid < L)  hist_sh[tid] = 0;
    #pragma unroll
    for (int i = tid; i < L + L * LP1; i += THREADS) A_sh[i] = A_scores[i];
    __syncthreads();

    int t = tick_sh;
    int y = IGNORE_LBL;
    if (t < NCHUNK) y = __ldcs(labels + (size_t)t * CHUNK + tid);   // in flight

    // ---- 2. 43 LSEs (warp w handles rows w, w+16, w+32) while labels fly ----
    #pragma unroll
    for (int rr = 0; rr < 3; rr++) {
        int r = wid + rr * WARPS;
        if (r <= L) {
            int n = (r == L) ? L : LP1;
            const float* row = (r == L) ? A_sh : (A_sh + L + r * LP1);
            float v0 = (lane < n)      ? row[lane]      : -1e30f;
            float v1 = (lane + 32 < n) ? row[lane + 32] : -1e30f;
            float m = fmaxf(v0, v1);
            #pragma unroll
            for (int o = 16; o > 0; o >>= 1)
                m = fmaxf(m, __shfl_xor_sync(0xffffffffu, m, o));
            float s = ((lane < n) ? __expf(v0 - m) : 0.f)
                    + ((lane + 32 < n) ? __expf(v1 - m) : 0.f);
            #pragma unroll
            for (int o = 16; o > 0; o >>= 1)
                s += __shfl_xor_sync(0xffffffffu, s, o);
            if (lane == 0) lse_sh[r] = m + __logf(s);
        }
    }
    __syncthreads();

    // ---- 3. chunk loop (pipelined: next labels prefetched mid-chunk) ----
    double local = 0.0;
    int    cnt   = 0;
    while (t < NCHUNK) {
        // issue emission gather for this chunk (labels have arrived)
        bool valid = (y != IGNORE_LBL);
        float e = 0.0f;
        if (valid) e = __ldcs(log_probs + ((size_t)t * CHUNK + tid) * C + y);

        // steal next chunk
        if (tid == 0) tick_sh = (int)atomicAdd(&g_work, 1u);

        // intra-warp transitions (raw) + histogram + segment endpoints
        cnt += valid ? 1 : 0;
        unsigned m = __ballot_sync(0xffffffffu, valid);
        unsigned rest = m & (0xFFFFFFFEu << lane);
        int partner = rest ? (__ffs(rest) - 1) : -1;
        int ynext = __shfl_sync(0xffffffffu, y, partner & 31);
        if (valid && partner >= 0) {
            local += (double)A_sh[L + (y - 1) * LP1 + (ynext - 1)];
            atomicAdd(&hist_sh[y - 1], 1);
        }
        int firstlane = __ffs(m) - 1;
        int lastlane  = 31 - __clz(m | 1u);
        int yf = __shfl_sync(0xffffffffu, y, firstlane & 31);
        int yl = __shfl_sync(0xffffffffu, y, lastlane & 31);
        if (lane == 0) {
            seg_f[wid] = m ? yf : -1;
            seg_l[wid] = m ? yl : -1;
        }
        __syncthreads();   // seg arrays + tick_sh ready

        // prefetch labels for next chunk
        int t2 = tick_sh;
        int y2 = IGNORE_LBL;
        if (t2 < NCHUNK) y2 = __ldcs(labels + (size_t)t2 * CHUNK + tid);

        // warp-boundary stitching (warp 0, 16 segments in parallel)
        if (wid == 0) {
            bool ne = (lane < WARPS) && (seg_f[lane] >= 0);
            unsigned sm = __ballot_sync(0xffffffffu, ne);
            if (ne) {
                unsigned low = sm & ((1u << lane) - 1u);
                if (low) {
                    int pred = 31 - __clz(low);
                    int y1 = seg_l[pred], yy = seg_f[lane];
                    local += (double)A_sh[L + (y1 - 1) * LP1 + (yy - 1)];
                    atomicAdd(&hist_sh[y1 - 1], 1);
                }
            }
            if (lane == 0) {
                g_first[t] = sm ? seg_f[__ffs(sm) - 1] : -1;
                g_last[t]  = sm ? seg_l[31 - __clz(sm)] : -1;
            }
        }

        local += (double)e;   // consume gather
        __syncthreads();      // seg arrays / tick_sh free for next iteration
        t = t2;
        y = y2;
    }

    // ---- 4. block reduce + per-block LSE correction ----
    #pragma unroll
    for (int o = 16; o > 0; o >>= 1) {
        local += __shfl_down_sync(0xffffffffu, local, o);
        cnt   += __shfl_down_sync(0xffffffffu, cnt, o);
    }
    if (lane == 0) { red[wid] = local; redc[wid] = cnt; }
    __syncthreads();
    if (wid == 0) {
        double v = (lane < WARPS) ? red[lane] : 0.0;
        int    c = (lane < WARPS) ? redc[lane] : 0;
        double corr = (lane < L) ? (double)hist_sh[lane] * (double)lse_sh[lane] : 0.0;
        if (lane + 32 < L) corr += (double)hist_sh[lane + 32] * (double)lse_sh[lane + 32];
        #pragma unroll
        for (int o = 16; o > 0; o >>= 1) {
            v    += __shfl_down_sync(0xffffffffu, v, o);
            c    += __shfl_down_sync(0xffffffffu, c, o);
            corr += __shfl_down_sync(0xffffffffu, corr, o);
        }
        if (lane == 0) {
            g_partial[blockIdx.x] = v - corr;   // normalized partial
            g_pcount[blockIdx.x]  = c;
        }
    }
    __threadfence();
    __syncthreads();
    if (tid == 0) {
        unsigned k = atomicAdd(&g_ticket, 1u);
        is_last = (k == NBLK - 1) ? 1 : 0;
    }
    __syncthreads();

    // ---- 5. last block: stitch chunk boundaries + start/final, finalize ----
    if (is_last) {
        __threadfence();

        double s_loc = 0.0; int c_loc = 0;
        for (int i = tid; i < NBLK; i += THREADS) {
            s_loc += g_partial[i];
            c_loc += g_pcount[i];
        }
        if (tid < B) {
            double s = 0.0; int prev = -1, f0 = -1;
            #pragma unroll 4
            for (int k = 0; k < 16; k++) {
                int idx = tid * 16 + k;
                int f = g_first[idx];
                if (f >= 0) {
                    if (prev >= 0)
                        s += (double)(A_sh[L + (prev - 1) * LP1 + (f - 1)] - lse_sh[prev - 1]);
                    else f0 = f;
                    prev = g_last[idx];
                }
            }
            if (f0 >= 0) {
                s += (double)(A_sh[f0 - 1] - lse_sh[L]);                          // start
                s += (double)(A_sh[L + (prev - 1) * LP1 + L] - lse_sh[prev - 1]); // final
            }
            s_loc += s;
        }
        // full-block reduce of (s_loc, c_loc)
        #pragma unroll
        for (int o = 16; o > 0; o >>= 1) {
            s_loc += __shfl_down_sync(0xffffffffu, s_loc, o);
            c_loc += __shfl_down_sync(0xffffffffu, c_loc, o);
        }
        if (lane == 0) { red[wid] = s_loc; redc[wid] = c_loc; }
        __syncthreads();
        if (wid == 0) {
            double s = (lane < WARPS) ? red[lane] : 0.0;
            int    c = (lane < WARPS) ? redc[lane] : 0;
            #pragma unroll
            for (int o = 16; o > 0; o >>= 1) {
                s += __shfl_down_sync(0xffffffffu, s, o);
                c += __shfl_down_sync(0xffffffffu, c, o);
            }
            if (lane == 0) {
                out[0] = (float)(s / (double)c);
                g_work   = 0;   // reset for graph replay
                g_ticket = 0;
            }
        }
    }
}

// ---------------------------------------------------------------------------
// Launch
// ---------------------------------------------------------------------------
extern "C" void kernel_launch(void* const* d_in, const int* in_sizes, int n_in,
                              void* d_out, int out_size) {
    const float* log_probs = (const float*)d_in[0];   // (B, S, C) f32
    const float* A_scores  = (const float*)d_in[1];   // (N_ARCS,) f32
    const int*   labels    = (const int*)d_in[2];     // (B, S) i32
    float* out = (float*)d_out;

    crf_fused_kernel<<<NBLK, THREADS>>>(log_probs, A_scores, labels, out);
}

// round 8
// speedup vs baseline: 1.3455x; 1.3325x over previous
#include <cuda_runtime.h>
#include <cuda_bf16.h>
#include <cstdint>

// Problem constants (fixed by the dataset)
#define B 64
#define S 8192
#define C 48
#define L 42
#define LP1 (L + 1)          // 43
#define IGNORE_LBL (-100)

#define ROW_THREADS 1024
#define ROW_WARPS   (ROW_THREADS / 32)   // 32
#define NCH   4                          // chunks per row
#define CHUNK (S / NCH)                  // 2048
#define SUBS  (CHUNK / ROW_THREADS)      // 2 positions per thread
#define NSEG  (SUBS * ROW_WARPS)         // 64 warp-segments per chunk
#define NCHT  (B * NCH)                  // 256 total chunks

// ---------------------------------------------------------------------------
// Device-global scratch (no allocations allowed)
// ---------------------------------------------------------------------------
__device__ double g_partial[NCHT];   // per-chunk score partial
__device__ int    g_pcount[NCHT];    // per-chunk valid-token count
__device__ int    g_first[NCHT];     // per-chunk first valid label (-1 if none)
__device__ int    g_last[NCHT];      // per-chunk last valid label
__device__ unsigned g_ticket;        // finish counter (reset by last block)

// Gather load with explicit 64B L2 fetch-size hint (vs default 128B line).
__device__ __forceinline__ float ld_gather_64B(const float* p) {
    float v;
    asm volatile("ld.global.L2::64B.f32 %0, [%1];" : "=f"(v) : "l"(p));
    return v;
}

// ---------------------------------------------------------------------------
// One block per (row, chunk). 256 blocks = 1 full wave at 2 blocks/SM.
// ---------------------------------------------------------------------------
__global__ __launch_bounds__(ROW_THREADS)
void crf_fused_kernel(const float* log_probs,
                      const float* __restrict__ A_scores,
                      const int*   __restrict__ labels,
                      float*       __restrict__ out) {
    const int cid  = blockIdx.x;        // chunk id
    const int b    = cid / NCH;         // batch row
    const int ch   = cid % NCH;         // chunk within row
    const int tid  = threadIdx.x;
    const int lane = tid & 31;
    const int wid  = tid >> 5;

    __shared__ float    A_sh[L + L * LP1];   // 1848 raw scores
    __shared__ float    lse_sh[LP1];
    __shared__ float    trans_sh[L * L];
    __shared__ float    start_sh[L];
    __shared__ float    fin_sh[L];
    __shared__ int      seg_first[NSEG];
    __shared__ int      seg_last[NSEG];
    __shared__ unsigned seg_mask[2];
    __shared__ double   red[ROW_WARPS];
    __shared__ int      redc[ROW_WARPS];
    __shared__ int      is_last;
    __shared__ double   row_sum[B];
    __shared__ int      row_cnt[B];

    // ---- 1. stage A_scores into shared; issue label loads (in flight) ----
    #pragma unroll
    for (int i = tid; i < L + L * LP1; i += ROW_THREADS) A_sh[i] = A_scores[i];

    const int* lab = labels + (size_t)b * S + (size_t)ch * CHUNK;
    int ys[SUBS];
    #pragma unroll
    for (int i = 0; i < SUBS; i++) ys[i] = __ldg(lab + i * ROW_THREADS + tid);

    __syncthreads();   // A_sh ready (label LDGs still in flight)

    // ---- 2. per-row log-sum-exp (warp w handles rows w, w+32) ----
    #pragma unroll
    for (int rr = 0; rr < 2; rr++) {
        int r = wid + rr * ROW_WARPS;
        if (r <= L) {
            int n = (r == L) ? L : LP1;
            const float* row = (r == L) ? A_sh : (A_sh + L + r * LP1);
            float v0 = (lane < n)      ? row[lane]      : -1e30f;
            float v1 = (lane + 32 < n) ? row[lane + 32] : -1e30f;
            float m = fmaxf(v0, v1);
            #pragma unroll
            for (int o = 16; o > 0; o >>= 1)
                m = fmaxf(m, __shfl_xor_sync(0xffffffffu, m, o));
            float s = ((lane < n) ? __expf(v0 - m) : 0.f)
                    + ((lane + 32 < n) ? __expf(v1 - m) : 0.f);
            #pragma unroll
            for (int o = 16; o > 0; o >>= 1)
                s += __shfl_xor_sync(0xffffffffu, s, o);
            if (lane == 0) lse_sh[r] = m + __logf(s);
        }
    }
    __syncthreads();

    // ---- 3. issue emission gathers NOW (labels have arrived), 64B hint ----
    const float* lpb = log_probs + (size_t)b * S * C + (size_t)ch * CHUNK * C;
    float emis[SUBS];
    #pragma unroll
    for (int i = 0; i < SUBS; i++) {
        int p = i * ROW_THREADS + tid;
        emis[i] = (ys[i] != IGNORE_LBL)
                ? ld_gather_64B(lpb + (size_t)p * C + ys[i]) : 0.0f;
    }

    // ---- 4. normalized tables (overlaps gather flight) ----
    #pragma unroll
    for (int i = tid; i < L * L; i += ROW_THREADS) {
        int r = i / L, c = i % L;
        trans_sh[i] = A_sh[L + r * LP1 + c] - lse_sh[r];
    }
    if (tid < L) {
        start_sh[tid] = A_sh[tid] - lse_sh[L];
        fin_sh[tid]   = A_sh[L + tid * LP1 + L] - lse_sh[tid];
    }
    __syncthreads();

    // ---- 5. intra-warp transitions + warp-segment endpoints (no emis dep) ----
    double local = 0.0;
    int    cnt   = 0;
    #pragma unroll
    for (int i = 0; i < SUBS; i++) {
        int y = ys[i];
        bool valid = (y != IGNORE_LBL);
        cnt += valid ? 1 : 0;

        unsigned m = __ballot_sync(0xffffffffu, valid);
        unsigned rest = m & (0xFFFFFFFEu << lane);  // valid lanes strictly after me
        int partner = rest ? (__ffs(rest) - 1) : -1;
        int ynext = __shfl_sync(0xffffffffu, y, partner & 31);
        if (valid && partner >= 0)
            local += (double)trans_sh[(y - 1) * L + (ynext - 1)];

        int firstlane = __ffs(m) - 1;
        int lastlane  = 31 - __clz(m | 1u);
        int yf = __shfl_sync(0xffffffffu, y, firstlane & 31);
        int yl = __shfl_sync(0xffffffffu, y, lastlane & 31);
        if (lane == 0) {
            int seg = i * ROW_WARPS + wid;       // segments in position order
            seg_first[seg] = m ? yf : -1;
            seg_last[seg]  = m ? yl : -1;
        }
    }
    __syncthreads();

    // ---- 6. PARALLEL warp-boundary stitching (threads 0..63) ----
    if (tid < 64) {
        bool ne = (seg_first[tid] >= 0);
        unsigned m = __ballot_sync(0xffffffffu, ne);
        if ((tid & 31) == 0) seg_mask[tid >> 5] = m;
    }
    __syncthreads();
    if (tid < NSEG) {
        int s = tid;
        if (seg_first[s] >= 0) {
            unsigned low = (s & 31) ? (seg_mask[s >> 5] & ((1u << (s & 31)) - 1u)) : 0u;
            int pred = -1;
            if (low)                         pred = (s & ~31) + (31 - __clz(low));
            else if (s >= 32 && seg_mask[0]) pred = 31 - __clz(seg_mask[0]);
            if (pred >= 0)
                local += (double)trans_sh[(seg_last[pred] - 1) * L + (seg_first[s] - 1)];
        }
    }
    if (tid == 0) {
        unsigned m0 = seg_mask[0], m1 = seg_mask[1];
        int bf = -1, bl = -1;
        if (m0)      bf = seg_first[__ffs(m0) - 1];
        else if (m1) bf = seg_first[32 + __ffs(m1) - 1];
        if (m1)      bl = seg_last[32 + 31 - __clz(m1)];
        else if (m0) bl = seg_last[31 - __clz(m0)];
        g_first[cid] = bf;
        g_last[cid]  = bl;
    }

    // ---- 7. fold emissions in (gathers have had table+ballot time to land) ----
    #pragma unroll
    for (int i = 0; i < SUBS; i++) local += (double)emis[i];

    // ---- 8. block reduction (double + int) ----
    #pragma unroll
    for (int o = 16; o > 0; o >>= 1) {
        local += __shfl_down_sync(0xffffffffu, local, o);
        cnt   += __shfl_down_sync(0xffffffffu, cnt, o);
    }
    if (lane == 0) { red[wid] = local; redc[wid] = cnt; }
    __syncthreads();
    if (wid == 0) {
        double v = red[lane];
        int    c = redc[lane];
        #pragma unroll
        for (int o = 16; o > 0; o >>= 1) {
            v += __shfl_down_sync(0xffffffffu, v, o);
            c += __shfl_down_sync(0xffffffffu, c, o);
        }
        if (lane == 0) {
            g_partial[cid] = v;
            g_pcount[cid]  = c;
            __threadfence();
            unsigned t = atomicAdd(&g_ticket, 1u);
            is_last = (t == NCHT - 1) ? 1 : 0;
        }
    }
    __syncthreads();

    // ---- 9. last block: stitch chunk boundaries + start/final, finalize ----
    if (is_last) {
        if (tid < B) {
            double s = 0.0; int c = 0, prev = -1, f0 = -1;
            #pragma unroll
            for (int k = 0; k < NCH; k++) {
                int idx = tid * NCH + k;
                s += g_partial[idx];
                c += g_pcount[idx];
                int f = g_first[idx];
                if (f >= 0) {
                    if (prev >= 0) s += (double)trans_sh[(prev - 1) * L + (f - 1)];
                    else           f0 = f;
                    prev = g_last[idx];
                }
            }
            if (f0 >= 0) s += (double)start_sh[f0 - 1] + (double)fin_sh[prev - 1];
            row_sum[tid] = s;
            row_cnt[tid] = c;
        }
        __syncthreads();
        if (wid == 0) {
            double s = row_sum[lane] + row_sum[lane + 32];
            int    c = row_cnt[lane] + row_cnt[lane + 32];
            #pragma unroll
            for (int o = 16; o > 0; o >>= 1) {
                s += __shfl_down_sync(0xffffffffu, s, o);
                c += __shfl_down_sync(0xffffffffu, c, o);
            }
            if (lane == 0) {
                out[0] = (float)(s / (double)c);
                g_ticket = 0;    // reset for graph replay
            }
        }
    }
}

// ---------------------------------------------------------------------------
// Launch
// ---------------------------------------------------------------------------
extern "C" void kernel_launch(void* const* d_in, const int* in_sizes, int n_in,
                              void* d_out, int out_size) {
    const float* log_probs = (const float*)d_in[0];   // (B, S, C) f32
    const float* A_scores  = (const float*)d_in[1];   // (N_ARCS,) f32
    const int*   labels    = (const int*)d_in[2];     // (B, S) i32
    float* out = (float*)d_out;

    crf_fused_kernel<<<NCHT, ROW_THREADS>>>(log_probs, A_scores, labels, out);
}